// round 16
// baseline (speedup 1.0000x reference)
#include <cuda_runtime.h>
#include <math.h>
#include <stdint.h>

#define BATCH 8
#define SEQ   256
#define F0    512
#define F1    256
#define F2    128
#define KMAX  30
#define DPB   8       // dpall blocks per batch
#define BIGF  3.0e38f

// ---- scratch (__device__ globals; no allocations allowed) ----
__device__ float g_h[BATCH*SEQ*F1];
__device__ float g_z[BATCH*SEQ*F2];
__device__ float g_P[BATCH*SEQ*SEQ];
__device__ float g_Pt[BATCH*SEQ*SEQ];       // transpose of P
__device__ float g_Pdiag[BATCH][SEQ];       // P[i][i]
__device__ float g_seg[BATCH][DPB][SEQ];    // per-segment row-scan totals
__device__ int   g_flagZ[BATCH][DPB];       // z chunk ready
__device__ int   g_flagS[BATCH][DPB];       // seg totals ready
__device__ int   g_flagP[BATCH][DPB];       // P rows of segment ready
__device__ float g_part[BATCH][DPB][SEQ];   // softmax partials
__device__ int   g_ctrF[BATCH];             // finalize arrival ctr (monotone)

// dpall dynamic smem (floats):
//  [0, 40960)   tri (width-classed; INF-filled late). Early overlays:
//    T[32][256] @0, OFFQ[4][256] @8192, OFF @9216,
//    corrtile[32][256] @16384, zown[32][128] @24576,
//    BsW[16][128] / BsC[4][16][64] @28672, AsH[16][32] @33024, sdiag @33664.
//    sacc[32][256] overlay @0 after softmax.
//  [40960, 48760)  sCs: 30 x 260 (data ptr +kk*260+4, Cs[i]=C[kk][i+1])
//  [48760, 49016)  sPd[256]
#define TRI_N    40960
#define SC_OFF   40960
#define SPD_OFF  48760
#define DSM_FLOATS 49016
#define DSM_BYTES  (DSM_FLOATS*4)

// warp-wide float min via redux.sync.min.s32 with monotone bit mapping
__device__ __forceinline__ float warp_min_redux(float mn) {
    int u = __float_as_int(mn);
    u ^= (u >> 31) & 0x7fffffff;
    int r;
    asm volatile("redux.sync.min.s32 %0, %1, 0xffffffff;" : "=r"(r) : "r"(u));
    r ^= (r >> 31) & 0x7fffffff;
    return __int_as_float(r);
}

// ============================================================
// GEMM1: h = relu(x @ W0 + b0). Scalar FFMA, 64x64 tile, BK=16.
// Block (0,0) zeroes the dpall pipeline flags for this replay.
// ============================================================
__global__ __launch_bounds__(256) void gemm_kernel(
    const float* __restrict__ A, const float* __restrict__ B,
    const float* __restrict__ bias, float* __restrict__ C,
    int M, int N, int K)
{
    __shared__ float As[16][64];
    __shared__ float Bs[16][64];
    const int m0 = blockIdx.y * 64, n0 = blockIdx.x * 64;
    const int tid = threadIdx.x;
    const int ty = tid >> 4, tx = tid & 15;
    const int arow = tid >> 2, akq = tid & 3;
    const int bkr  = tid >> 4, bnq = tid & 15;

    if (blockIdx.x == 0 && blockIdx.y == 0) {
        for (int i = tid; i < BATCH*DPB; i += 256) {
            ((int*)g_flagZ)[i] = 0;
            ((int*)g_flagS)[i] = 0;
            ((int*)g_flagP)[i] = 0;
        }
    }

    float acc[4][4] = {};

    for (int k0 = 0; k0 < K; k0 += 16) {
        float4 va = *(const float4*)(A + (size_t)(m0 + arow) * K + k0 + akq * 4);
        As[akq*4+0][arow] = va.x; As[akq*4+1][arow] = va.y;
        As[akq*4+2][arow] = va.z; As[akq*4+3][arow] = va.w;
        float4 vb = *(const float4*)(B + (size_t)(k0 + bkr) * N + n0 + bnq * 4);
        *(float4*)&Bs[bkr][bnq*4] = vb;
        __syncthreads();
        #pragma unroll
        for (int k = 0; k < 16; k++) {
            float4 a4 = *(const float4*)&As[k][ty*4];
            float4 b4 = *(const float4*)&Bs[k][tx*4];
            float av[4] = {a4.x, a4.y, a4.z, a4.w};
            float bv[4] = {b4.x, b4.y, b4.z, b4.w};
            #pragma unroll
            for (int r = 0; r < 4; r++)
                #pragma unroll
                for (int c = 0; c < 4; c++)
                    acc[r][c] += av[r] * bv[c];
        }
        __syncthreads();
    }

    #pragma unroll
    for (int r = 0; r < 4; r++) {
        int m = m0 + ty*4 + r;
        #pragma unroll
        for (int c = 0; c < 4; c++) {
            int n = n0 + tx*4 + c;
            float v = fmaxf(acc[r][c] + bias[n], 0.0f);
            C[(size_t)m * N + n] = v;
        }
    }
}

// ============================================================
// dpall: z-chunk GEMM -> z exchange -> diag + corr tile (local)
// -> D/scan -> P exchange -> width-classed tri -> redundant
// local min-DP -> fused softmax -> fused finalize.
// Grid (BATCH, DPB), 1024 threads.
// ============================================================
__global__ __launch_bounds__(1024) void dpall_kernel(
    float* __restrict__ out,
    const float* __restrict__ W1, const float* __restrict__ b1)
{
    extern __shared__ float sm[];
    float* tri         = sm;
    float (*T)[SEQ]    = (float(*)[SEQ])sm;                 // scan overlay
    float (*OFFQ)[SEQ] = (float(*)[SEQ])(sm + 8192);
    float *OFF         = sm + 9216;
    float *corrtile    = sm + 16384;                        // [32][256]
    float *zown        = sm + 24576;                        // [32][128]
    float *BsW         = sm + 28672;                        // [16][128]
    float (*BsC)[16][64] = (float(*)[16][64])(sm + 28672);  // [4][16][64]
    float *AsH         = sm + 33024;                        // [16][32]
    float *sdiag       = sm + 33664;                        // [256]
    float *sCs         = sm + SC_OFF;
    float *sPd         = sm + SPD_OFF;

    const int b = blockIdx.x, g = blockIdx.y;
    const int tid = threadIdx.x, w = tid >> 5, l = tid & 31;
    const int n0 = g * 32;

    // ---- phase 0a: z chunk = h[rows n0..n0+32) @ W1 + b1 ----
    {
        const float* hB = g_h + ((size_t)b * SEQ + n0) * F1;
        const int zr = tid >> 5;           // row 0..31 (uniform per warp)
        const int zc = (tid & 31) * 4;     // col 0..124
        float az0 = 0.f, az1 = 0.f, az2 = 0.f, az3 = 0.f;
        for (int k0 = 0; k0 < F1; k0 += 16) {
            if (tid < 512) {
                int r = tid >> 4, kk = tid & 15;
                AsH[kk*32 + r] = hB[(size_t)r * F1 + k0 + kk];
            }
            {
                int kk = tid >> 6, c2 = (tid & 63) * 2;
                float2 wv = *(const float2*)(W1 + (size_t)(k0 + kk) * F2 + c2);
                BsW[kk*128 + c2]     = wv.x;
                BsW[kk*128 + c2 + 1] = wv.y;
            }
            __syncthreads();
            #pragma unroll
            for (int k = 0; k < 16; k++) {
                float a = AsH[k*32 + zr];
                float4 b4 = *(const float4*)(BsW + k*128 + zc);
                az0 += a * b4.x; az1 += a * b4.y;
                az2 += a * b4.z; az3 += a * b4.w;
            }
            __syncthreads();
        }
        float4 bb = *(const float4*)(b1 + zc);
        float4 zv = make_float4(az0 + bb.x, az1 + bb.y, az2 + bb.z, az3 + bb.w);
        *(float4*)(zown + zr*128 + zc) = zv;
        __stcg((float4*)(g_z + ((size_t)b * SEQ + n0 + zr) * F2 + zc), zv);
    }
    __syncthreads();
    if (tid == 0) { __threadfence(); *(volatile int*)&g_flagZ[b][g] = 1; }

    // ---- wait all z chunks ----
    if (w == 0 && l < DPB) {
        volatile int* f = &g_flagZ[b][l];
        while (*f == 0) { }
    }
    if (w == 0) { __syncwarp(); if (l == 0) __threadfence(); }
    __syncthreads();

    // ---- phase 0b: diag (redundant, 4 lanes per row) ----
    {
        const int i = tid >> 2, q = tid & 3;
        const float* zr_ = g_z + ((size_t)b * SEQ + i) * F2 + 32*q;
        float s = 0.f;
        #pragma unroll
        for (int f4 = 0; f4 < 8; f4++) {
            float4 v = __ldcg((const float4*)(zr_ + 4*f4));
            s += (v.x*v.x + v.y*v.y) + (v.z*v.z + v.w*v.w);
        }
        s += __shfl_xor_sync(0xffffffffu, s, 1);
        s += __shfl_xor_sync(0xffffffffu, s, 2);
        if (q == 0) sdiag[i] = s;
    }
    __syncthreads();

    // ---- phase 0c: corr tile [32 x 256] = zown @ z^T ----
    {
        const int ws = tid >> 8;           // 0..3: col group 64*ws
        const int t  = tid & 255;
        const int ty2 = t >> 4;            // rows 2ty2, 2ty2+1
        const int tx = t & 15;             // cols 64*ws + 4*tx
        const float* zB = g_z + (size_t)b * SEQ * F2;
        float a00=0,a01=0,a02=0,a03=0, a10=0,a11=0,a12=0,a13=0;
        for (int k0 = 0; k0 < F2; k0 += 16) {
            {
                int row = t >> 2, kq = t & 3;
                float4 v = __ldcg((const float4*)(zB + (size_t)(64*ws + row) * F2 + k0 + 4*kq));
                BsC[ws][4*kq+0][row] = v.x;
                BsC[ws][4*kq+1][row] = v.y;
                BsC[ws][4*kq+2][row] = v.z;
                BsC[ws][4*kq+3][row] = v.w;
            }
            __syncthreads();
            #pragma unroll
            for (int k = 0; k < 16; k++) {
                float a0 = zown[(2*ty2)*128 + k0 + k];
                float a1 = zown[(2*ty2+1)*128 + k0 + k];
                float4 b4 = *(const float4*)(&BsC[ws][k][4*tx]);
                a00 += a0*b4.x; a01 += a0*b4.y; a02 += a0*b4.z; a03 += a0*b4.w;
                a10 += a1*b4.x; a11 += a1*b4.y; a12 += a1*b4.z; a13 += a1*b4.w;
            }
            __syncthreads();
        }
        *(float4*)(corrtile + (2*ty2)*256   + 64*ws + 4*tx) = make_float4(a00,a01,a02,a03);
        *(float4*)(corrtile + (2*ty2+1)*256 + 64*ws + 4*tx) = make_float4(a10,a11,a12,a13);
    }
    __syncthreads();

    // ---- phase 1: D + within-quarter row-scan (from smem corr) ----
    {
        const int i = tid & 255, q = tid >> 8;
        const float di = sdiag[i];
        float run = 0.0f;
        #pragma unroll
        for (int r = 0; r < 8; r++) {
            float rs = rsqrtf(fmaxf(sdiag[n0 + q*8 + r] * di, 1e-8f));
            float d = 0.5f - 0.5f * (corrtile[(q*8 + r)*256 + i] * rs);
            run += d;
            T[q*8 + r][i] = run;
        }
        OFFQ[q][i] = run;
    }
    __syncthreads();
    if (tid < 256) {
        const int i = tid;
        float t0 = OFFQ[0][i], t1 = OFFQ[1][i], t2 = OFFQ[2][i], t3 = OFFQ[3][i];
        float o1 = t0, o2 = t0 + t1, o3 = o2 + t2;
        OFFQ[0][i] = 0.0f; OFFQ[1][i] = o1; OFFQ[2][i] = o2; OFFQ[3][i] = o3;
        __stcg(&g_seg[b][g][i], o3 + t3);
    }
    __syncthreads();
    if (tid == 0) { __threadfence(); *(volatile int*)&g_flagS[b][g] = 1; }

    // poison the C table while waiting
    for (int idx = tid; idx < KMAX*260; idx += 1024) sCs[idx] = BIGF;

    // ---- wait seg totals of lower blocks; build OFF ----
    if (w == 0 && l < g) {
        volatile int* f = &g_flagS[b][l];
        while (*f == 0) { }
    }
    if (w == 0) { __syncwarp(); if (l == 0) __threadfence(); }
    __syncthreads();
    if (tid < 256) {
        float o = 0.0f;
        for (int gp = 0; gp < g; gp++) o += __ldcg(&g_seg[b][gp][tid]);
        OFF[tid] = o;
    }
    __syncthreads();

    // ---- col-scan: warp w scans absolute row n0+w; write P/Pt/Pdiag ----
    {
        const int row = n0 + w;
        const int q = w >> 3;
        float v[8];
        #pragma unroll
        for (int j = 0; j < 8; j++) {
            int c = l*8 + j;
            v[j] = T[w][c] + OFFQ[q][c] + OFF[c];
        }
        #pragma unroll
        for (int j = 1; j < 8; j++) v[j] += v[j-1];
        float tot = v[7], inc = tot;
        #pragma unroll
        for (int d2 = 1; d2 < 32; d2 <<= 1) {
            float t2 = __shfl_up_sync(0xffffffffu, inc, d2);
            if (l >= d2) inc += t2;
        }
        float excl = inc - tot;
        #pragma unroll
        for (int j = 0; j < 8; j++) v[j] += excl;
        float* P = g_P + ((size_t)b * SEQ + row) * SEQ;
        #pragma unroll
        for (int j = 0; j < 8; j++) __stcg(&P[l*8 + j], v[j]);
        float* Pt = g_Pt + (size_t)b * SEQ * SEQ;
        #pragma unroll
        for (int j = 0; j < 8; j++) {
            int i = l*8 + j;
            __stcg(&Pt[(size_t)i * SEQ + row], v[j]);
            if (i == row) __stcg(&g_Pdiag[b][row], v[j]);
        }
    }
    __syncthreads();
    if (tid == 0) { __threadfence(); *(volatile int*)&g_flagP[b][g] = 1; }

    // ---- wait ALL P chunks ----
    if (w == 0 && l < DPB) {
        volatile int* f = &g_flagP[b][l];
        while (*f == 0) { }
    }
    if (w == 0) { __syncwarp(); if (l == 0) __threadfence(); }
    __syncthreads();

    // ---- stage Pdiag; INF-fill tri (kills all early overlays) ----
    if (tid < 256) sPd[tid] = __ldcg(&g_Pdiag[b][tid]);
    {
        float4 inf4 = make_float4(BIGF, BIGF, BIGF, BIGF);
        for (int idx = tid; idx < TRI_N/4; idx += 1024)
            ((float4*)tri)[idx] = inf4;
    }
    __syncthreads();

    // ---- build width-classed tri + C0 into sCs ----
    const float* Pg  = g_P  + (size_t)b * SEQ * SEQ;
    const float* Ptg = g_Pt + (size_t)b * SEQ * SEQ;
    float* Cs0 = sCs + 4;
    int on[8];
    #pragma unroll
    for (int m = 0; m < 8; m++) {
        const int n = w + 32*m;
        const int c = m >> 1;
        const int W = 256 - 64*c;
        const int base = (c == 0) ? 0 : (c == 1) ? 16384 : (c == 2) ? 28672 : 36864;
        on[m] = base + (n - 64*c) * W - 64*c;   // elem i lives at on[m] + i
        float* pr = tri + on[m];
        const float pd = (n == 0) ? 0.0f : sPd[n-1];
        const float* Prow  = Pg  + (size_t)(n-1) * SEQ;
        const float* Ptrow = Ptg + (size_t)(n-1) * SEQ;
        for (int i = n + l; i < SEQ; i += 32) {
            float a  = sPd[i];
            float bb = (n == 0) ? 0.0f : __ldcg(&Prow[i]);
            float cc = (n == 0) ? 0.0f : __ldcg(&Ptrow[i]);
            float val = ((a - bb) - cc) + pd;
            pr[i] = val;
            if (i == SEQ - 1) Cs0[n - 1] = val;
        }
    }
    __syncthreads();

    // ---- redundant local min-DP: 29 steps, classed widths ----
    #pragma unroll 1
    for (int kk = 1; kk < KMAX; kk++) {
        const int limit = SEQ - kk;
        const float* Cp = sCs + (kk-1)*260 + 4;
        float* Cc = sCs + kk*260 + 4;
        float4 cA = *(const float4*)(Cp + 4*l);
        float4 cM = *(const float4*)(Cp + 64 + 4*l);
        float4 cB = *(const float4*)(Cp + 128 + 4*l);
        float2 cP = *(const float2*)(Cp + 192 + 2*l);
        #pragma unroll
        for (int m = 0; m < 8; m++) {
            const int n = w + 32*m;
            if (n < limit) {
                const float* pr = tri + on[m];
                float mn;
                if (m < 2) {
                    float4 t0 = *(const float4*)(pr + 4*l);
                    float4 t1 = *(const float4*)(pr + 128 + 4*l);
                    float4 m4;
                    m4.x = fminf(t0.x + cA.x, t1.x + cB.x);
                    m4.y = fminf(t0.y + cA.y, t1.y + cB.y);
                    m4.z = fminf(t0.z + cA.z, t1.z + cB.z);
                    m4.w = fminf(t0.w + cA.w, t1.w + cB.w);
                    mn = fminf(fminf(m4.x, m4.y), fminf(m4.z, m4.w));
                } else if (m < 4) {
                    float4 t0 = *(const float4*)(pr + 64 + 4*l);
                    float2 p  = *(const float2*)(pr + 192 + 2*l);
                    float4 m4;
                    m4.x = t0.x + cM.x; m4.y = t0.y + cM.y;
                    m4.z = t0.z + cM.z; m4.w = t0.w + cM.w;
                    float mp = fminf(p.x + cP.x, p.y + cP.y);
                    mn = fminf(fminf(fminf(m4.x, m4.y), fminf(m4.z, m4.w)), mp);
                } else if (m < 6) {
                    float4 t1 = *(const float4*)(pr + 128 + 4*l);
                    float4 m4;
                    m4.x = t1.x + cB.x; m4.y = t1.y + cB.y;
                    m4.z = t1.z + cB.z; m4.w = t1.w + cB.w;
                    mn = fminf(fminf(m4.x, m4.y), fminf(m4.z, m4.w));
                } else {
                    float2 p = *(const float2*)(pr + 192 + 2*l);
                    mn = fminf(p.x + cP.x, p.y + cP.y);
                }
                mn = warp_min_redux(mn);
                if (l == 0) Cc[n - 1] = mn;
            }
        }
        __syncthreads();
    }

    // ---- fused softmax: warp w owns row wb = g + 8w ----
    const int wb = g + 8*w;
    const int cw = wb >> 6;
    const int baseS = (cw == 0) ? 0 : (cw == 1) ? 16384 : (cw == 2) ? 28672 : 36864;
    const float* prS = tri + baseS + (wb - 64*cw) * (256 - 64*cw) - 64*cw;
    float4 acc0 = make_float4(0,0,0,0);
    float2 accP = make_float2(0,0);
    float4 acc1 = make_float4(0,0,0,0);
    #pragma unroll 1
    for (int kk = 1; kk < KMAX; kk++) {
        const int limit = SEQ - kk;
        if (wb >= limit) break;
        const float* Cp = sCs + (kk-1)*260 + 4;
        const float mn = (sCs + kk*260 + 4)[wb - 1];
        float s = 0.0f;
        float4 e0 = make_float4(0,0,0,0), e1 = make_float4(0,0,0,0);
        float2 eP = make_float2(0,0);
        if (cw == 0) {
            float4 cA = *(const float4*)(Cp + 4*l);
            float4 t = *(const float4*)(prS + 4*l);
            float4 x;
            x.x = (mn - t.x) - cA.x; x.y = (mn - t.y) - cA.y;
            x.z = (mn - t.z) - cA.z; x.w = (mn - t.w) - cA.w;
            float xm = fmaxf(fmaxf(x.x, x.y), fmaxf(x.z, x.w));
            if (__any_sync(0xffffffffu, xm > -87.0f)) {
                e0.x = __expf(x.x); e0.y = __expf(x.y);
                e0.z = __expf(x.z); e0.w = __expf(x.w);
                s += (e0.x + e0.y) + (e0.z + e0.w);
            }
            float4 cB = *(const float4*)(Cp + 128 + 4*l);
            float4 t1 = *(const float4*)(prS + 128 + 4*l);
            float4 y;
            y.x = (mn - t1.x) - cB.x; y.y = (mn - t1.y) - cB.y;
            y.z = (mn - t1.z) - cB.z; y.w = (mn - t1.w) - cB.w;
            float ym = fmaxf(fmaxf(y.x, y.y), fmaxf(y.z, y.w));
            if (__any_sync(0xffffffffu, ym > -87.0f)) {
                e1.x = __expf(y.x); e1.y = __expf(y.y);
                e1.z = __expf(y.z); e1.w = __expf(y.w);
                s += (e1.x + e1.y) + (e1.z + e1.w);
            }
        } else if (cw == 1) {
            float4 cM = *(const float4*)(Cp + 64 + 4*l);
            float4 t = *(const float4*)(prS + 64 + 4*l);
            float4 x;
            x.x = (mn - t.x) - cM.x; x.y = (mn - t.y) - cM.y;
            x.z = (mn - t.z) - cM.z; x.w = (mn - t.w) - cM.w;
            float xm = fmaxf(fmaxf(x.x, x.y), fmaxf(x.z, x.w));
            if (__any_sync(0xffffffffu, xm > -87.0f)) {
                e0.x = __expf(x.x); e0.y = __expf(x.y);
                e0.z = __expf(x.z); e0.w = __expf(x.w);
                s += (e0.x + e0.y) + (e0.z + e0.w);
            }
            float2 cP = *(const float2*)(Cp + 192 + 2*l);
            float2 p = *(const float2*)(prS + 192 + 2*l);
            float2 xp;
            xp.x = (mn - p.x) - cP.x; xp.y = (mn - p.y) - cP.y;
            if (__any_sync(0xffffffffu, fmaxf(xp.x, xp.y) > -87.0f)) {
                eP.x = __expf(xp.x); eP.y = __expf(xp.y);
                s += eP.x + eP.y;
            }
        } else if (cw == 2) {
            float4 cB = *(const float4*)(Cp + 128 + 4*l);
            float4 t1 = *(const float4*)(prS + 128 + 4*l);
            float4 y;
            y.x = (mn - t1.x) - cB.x; y.y = (mn - t1.y) - cB.y;
            y.z = (mn - t1.z) - cB.z; y.w = (mn - t1.w) - cB.w;
            float ym = fmaxf(fmaxf(y.x, y.y), fmaxf(y.z, y.w));
            if (__any_sync(0xffffffffu, ym > -87.0f)) {
                e1.x = __expf(y.x); e1.y = __expf(y.y);
                e1.z = __expf(y.z); e1.w = __expf(y.w);
                s += (e1.x + e1.y) + (e1.z + e1.w);
            }
        } else {
            float2 cP = *(const float2*)(Cp + 192 + 2*l);
            float2 p = *(const float2*)(prS + 192 + 2*l);
            float2 xp;
            xp.x = (mn - p.x) - cP.x; xp.y = (mn - p.y) - cP.y;
            if (__any_sync(0xffffffffu, fmaxf(xp.x, xp.y) > -87.0f)) {
                eP.x = __expf(xp.x); eP.y = __expf(xp.y);
                s += eP.x + eP.y;
            }
        }
        #pragma unroll
        for (int o = 16; o > 0; o >>= 1)
            s += __shfl_xor_sync(0xffffffffu, s, o);
        float inv = __fdividef(1.0f, s);
        acc0.x += e0.x * inv; acc0.y += e0.y * inv;
        acc0.z += e0.z * inv; acc0.w += e0.w * inv;
        acc1.x += e1.x * inv; acc1.y += e1.y * inv;
        acc1.z += e1.z * inv; acc1.w += e1.w * inv;
        accP.x += eP.x * inv; accP.y += eP.y * inv;
    }

    // ---- scatter to sacc (overlays tri), column-reduce -> partials ----
    __syncthreads();
    float* sacc = tri;
    float* srow = sacc + w*256;
    *(float4*)(srow + 4*l)       = make_float4(0,0,0,0);
    *(float4*)(srow + 128 + 4*l) = make_float4(0,0,0,0);
    if (cw == 0) {
        *(float4*)(srow + 4*l)       = acc0;
        *(float4*)(srow + 128 + 4*l) = acc1;
    } else if (cw == 1) {
        *(float4*)(srow + 64 + 4*l)  = acc0;
        *(float2*)(srow + 192 + 2*l) = accP;
    } else if (cw == 2) {
        *(float4*)(srow + 128 + 4*l) = acc1;
    } else {
        *(float2*)(srow + 192 + 2*l) = accP;
    }
    __syncthreads();
    if (tid < 256) {
        float sum = 0.0f;
        #pragma unroll
        for (int ww = 0; ww < 32; ww++) sum += sacc[ww*256 + tid];
        g_part[b][g][tid] = sum;
    }
    __syncthreads();

    // ---- fused finalize: last arriving block per batch reduces ----
    __shared__ int sLast;
    if (tid == 0) {
        __threadfence();
        int old = atomicAdd(&g_ctrF[b], 1);
        sLast = ((old % DPB) == DPB - 1);
        if (sLast) __threadfence();
    }
    __syncthreads();
    if (sLast && tid < 256) {
        const int i = tid;
        float num = (i == SEQ - 1) ? (float)SEQ : 0.0f;
        #pragma unroll
        for (int p = 0; p < DPB; p++) num += __ldcg(&g_part[b][p][i]);
        int mm = min(KMAX - 1, SEQ - 1 - i);
        float cnt = (float)((i + 1) * mm + ((i == SEQ - 1) ? SEQ : 0));
        out[b*SEQ + i] = num / cnt;
    }
}

// ============================================================
extern "C" void kernel_launch(void* const* d_in, const int* in_sizes, int n_in,
                              void* d_out, int out_size)
{
    const float* x  = (const float*)d_in[0];
    const float* W0 = (const float*)d_in[1];
    const float* b0 = (const float*)d_in[2];
    const float* W1 = (const float*)d_in[3];
    const float* b1 = (const float*)d_in[4];
    float* out = (float*)d_out;

    static float* p_h = nullptr;
    if (!p_h) {
        cudaGetSymbolAddress((void**)&p_h, g_h);
        cudaFuncSetAttribute(dpall_kernel,
                             cudaFuncAttributeMaxDynamicSharedMemorySize, DSM_BYTES);
    }

    gemm_kernel<<<dim3(F1/64, (BATCH*SEQ)/64), 256>>>(x, W0, b0, p_h, BATCH*SEQ, F1, F0);
    dpall_kernel<<<dim3(BATCH, DPB), 1024, DSM_BYTES>>>(out, W1, b1);
}

// round 17
// speedup vs baseline: 1.2929x; 1.2929x over previous
#include <cuda_runtime.h>
#include <math.h>
#include <stdint.h>

#define BATCH 8
#define SEQ   256
#define F0    512
#define F1    256
#define F2    128
#define KMAX  30
#define DPB   16      // dpall blocks per batch (redundant DP, split softmax)
#define BIGF  3.0e38f

// ---- scratch (__device__ globals; no allocations allowed) ----
__device__ float g_h[BATCH*SEQ*F1];
__device__ float g_z[BATCH*SEQ*F2];
__device__ float g_corr[BATCH*SEQ*SEQ];
__device__ float g_P[BATCH*SEQ*SEQ];
__device__ float g_Pt[BATCH*SEQ*SEQ];       // transpose of P
__device__ float g_Pdiag[BATCH][SEQ];       // P[i][i]
__device__ float g_diag[BATCH][SEQ];        // diag of corr
__device__ float g_seg[BATCH][DPB][SEQ];    // per-segment row-scan totals
__device__ int   g_flagS[BATCH][DPB];       // seg totals ready
__device__ int   g_flagP[BATCH][DPB];       // P rows of segment ready
__device__ float g_part[BATCH][DPB][SEQ];   // softmax partials
__device__ int   g_ctrF[BATCH];             // finalize arrival ctr (monotone)

// dpall dynamic smem (floats):
//  tri (width-classed): class c=n>>6, W(c)=256-64c, bases {0,16384,28672,36864}.
//  Early overlays: T[16][256] @0, OFFQ[4][256] @8192, OFF @9216, sdn @9472.
//  sacc[32][256] overlay @0 after softmax.
//  sCs: 30 x 260 (data ptr +kk*260+4, Cs[i]=C[kk][i+1]); sPd[256].
#define TRI_N    40960
#define SC_OFF   40960
#define SPD_OFF  48760
#define DSM_FLOATS 49016
#define DSM_BYTES  (DSM_FLOATS*4)

// warp-wide float min via redux.sync.min.s32 with monotone bit mapping
__device__ __forceinline__ float warp_min_redux(float mn) {
    int u = __float_as_int(mn);
    u ^= (u >> 31) & 0x7fffffff;
    int r;
    asm volatile("redux.sync.min.s32 %0, %1, 0xffffffff;" : "=r"(r) : "r"(u));
    r ^= (r >> 31) & 0x7fffffff;
    return __int_as_float(r);
}

// ============================================================
// GEMM: scalar FFMA, 64x64 tile, BK=16, 256 thr, 4x4/thread.
// ============================================================
template<int RELU>
__global__ __launch_bounds__(256) void gemm_kernel(
    const float* __restrict__ A, const float* __restrict__ B,
    const float* __restrict__ bias, float* __restrict__ C,
    int M, int N, int K)
{
    __shared__ float As[16][64];
    __shared__ float Bs[16][64];
    const int m0 = blockIdx.y * 64, n0 = blockIdx.x * 64;
    const int tid = threadIdx.x;
    const int ty = tid >> 4, tx = tid & 15;
    const int arow = tid >> 2, akq = tid & 3;
    const int bkr  = tid >> 4, bnq = tid & 15;

    float acc[4][4] = {};

    for (int k0 = 0; k0 < K; k0 += 16) {
        float4 va = *(const float4*)(A + (size_t)(m0 + arow) * K + k0 + akq * 4);
        As[akq*4+0][arow] = va.x; As[akq*4+1][arow] = va.y;
        As[akq*4+2][arow] = va.z; As[akq*4+3][arow] = va.w;
        float4 vb = *(const float4*)(B + (size_t)(k0 + bkr) * N + n0 + bnq * 4);
        *(float4*)&Bs[bkr][bnq*4] = vb;
        __syncthreads();
        #pragma unroll
        for (int k = 0; k < 16; k++) {
            float4 a4 = *(const float4*)&As[k][ty*4];
            float4 b4 = *(const float4*)&Bs[k][tx*4];
            float av[4] = {a4.x, a4.y, a4.z, a4.w};
            float bv[4] = {b4.x, b4.y, b4.z, b4.w};
            #pragma unroll
            for (int r = 0; r < 4; r++)
                #pragma unroll
                for (int c = 0; c < 4; c++)
                    acc[r][c] += av[r] * bv[c];
        }
        __syncthreads();
    }

    #pragma unroll
    for (int r = 0; r < 4; r++) {
        int m = m0 + ty*4 + r;
        #pragma unroll
        for (int c = 0; c < 4; c++) {
            int n = n0 + tx*4 + c;
            float v = acc[r][c] + bias[n];
            if (RELU) v = fmaxf(v, 0.0f);
            C[(size_t)m * N + n] = v;
        }
    }
}

// ============================================================
// corr[b] = z_b @ z_b^T, scalar FFMA. Diag capture + flag zeroing.
// ============================================================
__global__ __launch_bounds__(256) void syrk_kernel()
{
    __shared__ float As[16][64];
    __shared__ float Bs[16][64];
    const int bz = blockIdx.z;
    const float* Z = g_z + (size_t)bz * SEQ * F2;
    float* C = g_corr + (size_t)bz * SEQ * SEQ;
    const int m0 = blockIdx.y * 64, n0 = blockIdx.x * 64;
    const int tid = threadIdx.x;
    const int ty = tid >> 4, tx = tid & 15;
    const int row = tid >> 2, kq = tid & 3;

    if (blockIdx.x == 0 && blockIdx.y == 0 && bz == 0) {
        for (int i = tid; i < BATCH*DPB; i += 256) {
            ((int*)g_flagS)[i] = 0;
            ((int*)g_flagP)[i] = 0;
        }
    }

    float acc[4][4] = {};

    for (int k0 = 0; k0 < F2; k0 += 16) {
        float4 va = *(const float4*)(Z + (size_t)(m0 + row) * F2 + k0 + kq * 4);
        As[kq*4+0][row] = va.x; As[kq*4+1][row] = va.y;
        As[kq*4+2][row] = va.z; As[kq*4+3][row] = va.w;
        float4 vb = *(const float4*)(Z + (size_t)(n0 + row) * F2 + k0 + kq * 4);
        Bs[kq*4+0][row] = vb.x; Bs[kq*4+1][row] = vb.y;
        Bs[kq*4+2][row] = vb.z; Bs[kq*4+3][row] = vb.w;
        __syncthreads();
        #pragma unroll
        for (int k = 0; k < 16; k++) {
            float4 a4 = *(const float4*)&As[k][ty*4];
            float4 b4 = *(const float4*)&Bs[k][tx*4];
            float av[4] = {a4.x, a4.y, a4.z, a4.w};
            float bv[4] = {b4.x, b4.y, b4.z, b4.w};
            #pragma unroll
            for (int r = 0; r < 4; r++)
                #pragma unroll
                for (int c = 0; c < 4; c++)
                    acc[r][c] += av[r] * bv[c];
        }
        __syncthreads();
    }

    #pragma unroll
    for (int r = 0; r < 4; r++) {
        int m = m0 + ty*4 + r;
        #pragma unroll
        for (int c = 0; c < 4; c++) {
            int n = n0 + tx*4 + c;
            C[(size_t)m * SEQ + n] = acc[r][c];
            if (m == n) g_diag[bz][m] = acc[r][c];
        }
    }
}

// ============================================================
// dpall: scan(16 rows) -> P exchange -> width-classed tri ->
// redundant local min-DP -> warp-pair softmax -> fused finalize.
// Grid (BATCH, DPB=16), 1024 threads.
// ============================================================
__global__ __launch_bounds__(1024) void dpall_kernel(float* __restrict__ out)
{
    extern __shared__ float sm[];
    float* tri         = sm;
    float (*T)[SEQ]    = (float(*)[SEQ])sm;                 // scan overlay [16][256]
    float (*OFFQ)[SEQ] = (float(*)[SEQ])(sm + 8192);
    float *OFF         = sm + 9216;
    float *sdn         = sm + 9472;
    float *sCs         = sm + SC_OFF;
    float *sPd         = sm + SPD_OFF;

    const int b = blockIdx.x, g = blockIdx.y;
    const int tid = threadIdx.x, w = tid >> 5, l = tid & 31;
    const int n0 = g * 16;                    // this block's 16 scan rows

    // ---- phase 1: D + within-quarter row-scan (4 rows per quarter) ----
    if (tid < 16) sdn[tid] = g_diag[b][n0 + tid];
    __syncthreads();
    {
        const int i = tid & 255, q = tid >> 8;
        const float di = g_diag[b][i];
        const float* cb = g_corr + (size_t)b * SEQ * SEQ + (size_t)(n0 + q*4) * SEQ;
        float run = 0.0f;
        #pragma unroll
        for (int r = 0; r < 4; r++) {
            float rs = rsqrtf(fmaxf(sdn[q*4 + r] * di, 1e-8f));
            float d = 0.5f - 0.5f * (cb[r*SEQ + i] * rs);
            run += d;
            T[q*4 + r][i] = run;
        }
        OFFQ[q][i] = run;
    }
    __syncthreads();
    if (tid < 256) {
        const int i = tid;
        float t0 = OFFQ[0][i], t1 = OFFQ[1][i], t2 = OFFQ[2][i], t3 = OFFQ[3][i];
        float o1 = t0, o2 = t0 + t1, o3 = o2 + t2;
        OFFQ[0][i] = 0.0f; OFFQ[1][i] = o1; OFFQ[2][i] = o2; OFFQ[3][i] = o3;
        __stcg(&g_seg[b][g][i], o3 + t3);
    }
    __syncthreads();
    if (tid == 0) { __threadfence(); *(volatile int*)&g_flagS[b][g] = 1; }

    // poison the C table while waiting
    for (int idx = tid; idx < KMAX*260; idx += 1024) sCs[idx] = BIGF;

    // ---- wait seg totals of lower blocks; build OFF ----
    if (w == 0 && l < g) {
        volatile int* f = &g_flagS[b][l];
        while (*f == 0) { }
    }
    if (w == 0) { __syncwarp(); if (l == 0) __threadfence(); }
    __syncthreads();
    if (tid < 256) {
        float o = 0.0f;
        for (int gp = 0; gp < g; gp++) o += __ldcg(&g_seg[b][gp][tid]);
        OFF[tid] = o;
    }
    __syncthreads();

    // ---- col-scan: warps 0-15, warp w scans absolute row n0+w ----
    if (w < 16) {
        const int row = n0 + w;
        const int q = w >> 2;
        float v[8];
        #pragma unroll
        for (int j = 0; j < 8; j++) {
            int c = l*8 + j;
            v[j] = T[w][c] + OFFQ[q][c] + OFF[c];
        }
        #pragma unroll
        for (int j = 1; j < 8; j++) v[j] += v[j-1];
        float tot = v[7], inc = tot;
        #pragma unroll
        for (int d2 = 1; d2 < 32; d2 <<= 1) {
            float t2 = __shfl_up_sync(0xffffffffu, inc, d2);
            if (l >= d2) inc += t2;
        }
        float excl = inc - tot;
        #pragma unroll
        for (int j = 0; j < 8; j++) v[j] += excl;
        float* P = g_P + ((size_t)b * SEQ + row) * SEQ;
        #pragma unroll
        for (int j = 0; j < 8; j++) __stcg(&P[l*8 + j], v[j]);
        float* Pt = g_Pt + (size_t)b * SEQ * SEQ;
        #pragma unroll
        for (int j = 0; j < 8; j++) {
            int i = l*8 + j;
            __stcg(&Pt[(size_t)i * SEQ + row], v[j]);
            if (i == row) __stcg(&g_Pdiag[b][row], v[j]);
        }
    }
    __syncthreads();
    if (tid == 0) { __threadfence(); *(volatile int*)&g_flagP[b][g] = 1; }

    // ---- wait ALL P chunks ----
    if (w == 0 && l < DPB) {
        volatile int* f = &g_flagP[b][l];
        while (*f == 0) { }
    }
    if (w == 0) { __syncwarp(); if (l == 0) __threadfence(); }
    __syncthreads();

    // ---- stage Pdiag; INF-fill tri (kills scan overlay) ----
    if (tid < 256) sPd[tid] = __ldcg(&g_Pdiag[b][tid]);
    {
        float4 inf4 = make_float4(BIGF, BIGF, BIGF, BIGF);
        for (int idx = tid; idx < TRI_N/4; idx += 1024)
            ((float4*)tri)[idx] = inf4;
    }
    __syncthreads();

    // ---- build width-classed tri + C0 into sCs ----
    const float* Pg  = g_P  + (size_t)b * SEQ * SEQ;
    const float* Ptg = g_Pt + (size_t)b * SEQ * SEQ;
    float* Cs0 = sCs + 4;
    int on[8];
    #pragma unroll
    for (int m = 0; m < 8; m++) {
        const int n = w + 32*m;
        const int c = m >> 1;
        const int W = 256 - 64*c;
        const int base = (c == 0) ? 0 : (c == 1) ? 16384 : (c == 2) ? 28672 : 36864;
        on[m] = base + (n - 64*c) * W - 64*c;   // elem i lives at on[m] + i
        float* pr = tri + on[m];
        const float pd = (n == 0) ? 0.0f : sPd[n-1];
        const float* Prow  = Pg  + (size_t)(n-1) * SEQ;
        const float* Ptrow = Ptg + (size_t)(n-1) * SEQ;
        for (int i = n + l; i < SEQ; i += 32) {
            float a  = sPd[i];
            float bb = (n == 0) ? 0.0f : __ldcg(&Prow[i]);
            float cc = (n == 0) ? 0.0f : __ldcg(&Ptrow[i]);
            float val = ((a - bb) - cc) + pd;
            pr[i] = val;
            if (i == SEQ - 1) Cs0[n - 1] = val;
        }
    }
    __syncthreads();

    // ---- redundant local min-DP: 29 steps, classed widths ----
    #pragma unroll 1
    for (int kk = 1; kk < KMAX; kk++) {
        const int limit = SEQ - kk;
        const float* Cp = sCs + (kk-1)*260 + 4;
        float* Cc = sCs + kk*260 + 4;
        float4 cA = *(const float4*)(Cp + 4*l);
        float4 cM = *(const float4*)(Cp + 64 + 4*l);
        float4 cB = *(const float4*)(Cp + 128 + 4*l);
        float2 cP = *(const float2*)(Cp + 192 + 2*l);
        #pragma unroll
        for (int m = 0; m < 8; m++) {
            const int n = w + 32*m;
            if (n < limit) {
                const float* pr = tri + on[m];
                float mn;
                if (m < 2) {
                    float4 t0 = *(const float4*)(pr + 4*l);
                    float4 t1 = *(const float4*)(pr + 128 + 4*l);
                    float4 m4;
                    m4.x = fminf(t0.x + cA.x, t1.x + cB.x);
                    m4.y = fminf(t0.y + cA.y, t1.y + cB.y);
                    m4.z = fminf(t0.z + cA.z, t1.z + cB.z);
                    m4.w = fminf(t0.w + cA.w, t1.w + cB.w);
                    mn = fminf(fminf(m4.x, m4.y), fminf(m4.z, m4.w));
                } else if (m < 4) {
                    float4 t0 = *(const float4*)(pr + 64 + 4*l);
                    float2 p  = *(const float2*)(pr + 192 + 2*l);
                    float4 m4;
                    m4.x = t0.x + cM.x; m4.y = t0.y + cM.y;
                    m4.z = t0.z + cM.z; m4.w = t0.w + cM.w;
                    float mp = fminf(p.x + cP.x, p.y + cP.y);
                    mn = fminf(fminf(fminf(m4.x, m4.y), fminf(m4.z, m4.w)), mp);
                } else if (m < 6) {
                    float4 t1 = *(const float4*)(pr + 128 + 4*l);
                    float4 m4;
                    m4.x = t1.x + cB.x; m4.y = t1.y + cB.y;
                    m4.z = t1.z + cB.z; m4.w = t1.w + cB.w;
                    mn = fminf(fminf(m4.x, m4.y), fminf(m4.z, m4.w));
                } else {
                    float2 p = *(const float2*)(pr + 192 + 2*l);
                    mn = fminf(p.x + cP.x, p.y + cP.y);
                }
                mn = warp_min_redux(mn);
                if (l == 0) Cc[n - 1] = mn;
            }
        }
        __syncthreads();
    }

    // ---- warp-pair softmax: row wb = g + 16*(w&15); parity = w>>4
    //      picks kk subset (1+parity, step 2). accs merge in sacc. ----
    const int wb = g + 16*(w & 15);
    const int par = w >> 4;
    const int cw = wb >> 6;
    const int baseS = (cw == 0) ? 0 : (cw == 1) ? 16384 : (cw == 2) ? 28672 : 36864;
    const float* prS = tri + baseS + (wb - 64*cw) * (256 - 64*cw) - 64*cw;
    float4 acc0 = make_float4(0,0,0,0);
    float2 accP = make_float2(0,0);
    float4 acc1 = make_float4(0,0,0,0);
    #pragma unroll 1
    for (int kk = 1 + par; kk < KMAX; kk += 2) {
        const int limit = SEQ - kk;
        if (wb >= limit) break;
        const float* Cp = sCs + (kk-1)*260 + 4;
        const float mn = (sCs + kk*260 + 4)[wb - 1];
        float s = 0.0f;
        float4 e0 = make_float4(0,0,0,0), e1 = make_float4(0,0,0,0);
        float2 eP = make_float2(0,0);
        if (cw == 0) {
            float4 cA = *(const float4*)(Cp + 4*l);
            float4 t = *(const float4*)(prS + 4*l);
            float4 x;
            x.x = (mn - t.x) - cA.x; x.y = (mn - t.y) - cA.y;
            x.z = (mn - t.z) - cA.z; x.w = (mn - t.w) - cA.w;
            float xm = fmaxf(fmaxf(x.x, x.y), fmaxf(x.z, x.w));
            if (__any_sync(0xffffffffu, xm > -87.0f)) {
                e0.x = __expf(x.x); e0.y = __expf(x.y);
                e0.z = __expf(x.z); e0.w = __expf(x.w);
                s += (e0.x + e0.y) + (e0.z + e0.w);
            }
            float4 cB = *(const float4*)(Cp + 128 + 4*l);
            float4 t1 = *(const float4*)(prS + 128 + 4*l);
            float4 y;
            y.x = (mn - t1.x) - cB.x; y.y = (mn - t1.y) - cB.y;
            y.z = (mn - t1.z) - cB.z; y.w = (mn - t1.w) - cB.w;
            float ym = fmaxf(fmaxf(y.x, y.y), fmaxf(y.z, y.w));
            if (__any_sync(0xffffffffu, ym > -87.0f)) {
                e1.x = __expf(y.x); e1.y = __expf(y.y);
                e1.z = __expf(y.z); e1.w = __expf(y.w);
                s += (e1.x + e1.y) + (e1.z + e1.w);
            }
        } else if (cw == 1) {
            float4 cM = *(const float4*)(Cp + 64 + 4*l);
            float4 t = *(const float4*)(prS + 64 + 4*l);
            float4 x;
            x.x = (mn - t.x) - cM.x; x.y = (mn - t.y) - cM.y;
            x.z = (mn - t.z) - cM.z; x.w = (mn - t.w) - cM.w;
            float xm = fmaxf(fmaxf(x.x, x.y), fmaxf(x.z, x.w));
            if (__any_sync(0xffffffffu, xm > -87.0f)) {
                e0.x = __expf(x.x); e0.y = __expf(x.y);
                e0.z = __expf(x.z); e0.w = __expf(x.w);
                s += (e0.x + e0.y) + (e0.z + e0.w);
            }
            float2 cP = *(const float2*)(Cp + 192 + 2*l);
            float2 p = *(const float2*)(prS + 192 + 2*l);
            float2 xp;
            xp.x = (mn - p.x) - cP.x; xp.y = (mn - p.y) - cP.y;
            if (__any_sync(0xffffffffu, fmaxf(xp.x, xp.y) > -87.0f)) {
                eP.x = __expf(xp.x); eP.y = __expf(xp.y);
                s += eP.x + eP.y;
            }
        } else if (cw == 2) {
            float4 cB = *(const float4*)(Cp + 128 + 4*l);
            float4 t1 = *(const float4*)(prS + 128 + 4*l);
            float4 y;
            y.x = (mn - t1.x) - cB.x; y.y = (mn - t1.y) - cB.y;
            y.z = (mn - t1.z) - cB.z; y.w = (mn - t1.w) - cB.w;
            float ym = fmaxf(fmaxf(y.x, y.y), fmaxf(y.z, y.w));
            if (__any_sync(0xffffffffu, ym > -87.0f)) {
                e1.x = __expf(y.x); e1.y = __expf(y.y);
                e1.z = __expf(y.z); e1.w = __expf(y.w);
                s += (e1.x + e1.y) + (e1.z + e1.w);
            }
        } else {
            float2 cP = *(const float2*)(Cp + 192 + 2*l);
            float2 p = *(const float2*)(prS + 192 + 2*l);
            float2 xp;
            xp.x = (mn - p.x) - cP.x; xp.y = (mn - p.y) - cP.y;
            if (__any_sync(0xffffffffu, fmaxf(xp.x, xp.y) > -87.0f)) {
                eP.x = __expf(xp.x); eP.y = __expf(xp.y);
                s += eP.x + eP.y;
            }
        }
        #pragma unroll
        for (int o = 16; o > 0; o >>= 1)
            s += __shfl_xor_sync(0xffffffffu, s, o);
        float inv = __fdividef(1.0f, s);
        acc0.x += e0.x * inv; acc0.y += e0.y * inv;
        acc0.z += e0.z * inv; acc0.w += e0.w * inv;
        acc1.x += e1.x * inv; acc1.y += e1.y * inv;
        acc1.z += e1.z * inv; acc1.w += e1.w * inv;
        accP.x += eP.x * inv; accP.y += eP.y * inv;
    }

    // ---- scatter to sacc (overlays tri), column-reduce -> partials ----
    __syncthreads();
    float* sacc = tri;                        // 32 x 256 overlay
    float* srow = sacc + w*256;
    *(float4*)(srow + 4*l)       = make_float4(0,0,0,0);
    *(float4*)(srow + 128 + 4*l) = make_float4(0,0,0,0);
    if (cw == 0) {
        *(float4*)(srow + 4*l)       = acc0;
        *(float4*)(srow + 128 + 4*l) = acc1;
    } else if (cw == 1) {
        *(float4*)(srow + 64 + 4*l)  = acc0;
        *(float2*)(srow + 192 + 2*l) = accP;
    } else if (cw == 2) {
        *(float4*)(srow + 128 + 4*l) = acc1;
    } else {
        *(float2*)(srow + 192 + 2*l) = accP;
    }
    __syncthreads();
    if (tid < 256) {
        float sum = 0.0f;
        #pragma unroll
        for (int ww = 0; ww < 32; ww++) sum += sacc[ww*256 + tid];
        g_part[b][g][tid] = sum;
    }
    __syncthreads();

    // ---- fused finalize: last arriving block per batch reduces ----
    __shared__ int sLast;
    if (tid == 0) {
        __threadfence();
        int old = atomicAdd(&g_ctrF[b], 1);
        sLast = ((old % DPB) == DPB - 1);
        if (sLast) __threadfence();
    }
    __syncthreads();
    if (sLast && tid < 256) {
        const int i = tid;
        float num = (i == SEQ - 1) ? (float)SEQ : 0.0f;
        #pragma unroll
        for (int p = 0; p < DPB; p++) num += __ldcg(&g_part[b][p][i]);
        int mm = min(KMAX - 1, SEQ - 1 - i);
        float cnt = (float)((i + 1) * mm + ((i == SEQ - 1) ? SEQ : 0));
        out[b*SEQ + i] = num / cnt;
    }
}

// ============================================================
extern "C" void kernel_launch(void* const* d_in, const int* in_sizes, int n_in,
                              void* d_out, int out_size)
{
    const float* x  = (const float*)d_in[0];
    const float* W0 = (const float*)d_in[1];
    const float* b0 = (const float*)d_in[2];
    const float* W1 = (const float*)d_in[3];
    const float* b1 = (const float*)d_in[4];
    float* out = (float*)d_out;

    static float* p_h = nullptr;
    static float* p_z = nullptr;
    if (!p_h) {
        cudaGetSymbolAddress((void**)&p_h, g_h);
        cudaGetSymbolAddress((void**)&p_z, g_z);
        cudaFuncSetAttribute(dpall_kernel,
                             cudaFuncAttributeMaxDynamicSharedMemorySize, DSM_BYTES);
    }

    gemm_kernel<1><<<dim3(F1/64, (BATCH*SEQ)/64), 256>>>(x,   W0, b0, p_h, BATCH*SEQ, F1, F0);
    gemm_kernel<0><<<dim3(F2/64, (BATCH*SEQ)/64), 256>>>(p_h, W1, b1, p_z, BATCH*SEQ, F2, F1);
    syrk_kernel<<<dim3(SEQ/64, SEQ/64, BATCH), 256>>>();
    dpall_kernel<<<dim3(BATCH, DPB), 1024, DSM_BYTES>>>(out);
}